// round 1
// baseline (speedup 1.0000x reference)
#include <cuda_runtime.h>
#include <cstddef>

// Problem constants (fixed by the reference)
#define NB   4      // batches per warp (register blocking; amortizes weight LDS)
#define HD   32     // hidden dim
#define WIDF 64     // MLP width
#define CINC 3      // control channels

// Tsit5 tableau (fp32 of the double literals, matching jnp weak-typed fp32)
__device__ __constant__ float cA21 = 0.161f;
__device__ __constant__ float cA31 = -0.008480655492356989f;
__device__ __constant__ float cA32 = 0.335480655492357f;
__device__ __constant__ float cA41 = 2.8971530571054935f;
__device__ __constant__ float cA42 = -6.359448489975075f;
__device__ __constant__ float cA43 = 4.3622954328695815f;
__device__ __constant__ float cA51 = 5.325864828439257f;
__device__ __constant__ float cA52 = -11.748883564062828f;
__device__ __constant__ float cA53 = 7.4955393428898365f;
__device__ __constant__ float cA54 = -0.09249506636175525f;
__device__ __constant__ float cA61 = 5.86145544294642f;
__device__ __constant__ float cA62 = -12.92096931784711f;
__device__ __constant__ float cA63 = 8.159367898576159f;
__device__ __constant__ float cA64 = -0.071584973281401f;
__device__ __constant__ float cA65 = -0.028269050394068383f;
__device__ __constant__ float cB1 = 0.09646076681806523f;
__device__ __constant__ float cB2 = 0.01f;
__device__ __constant__ float cB3 = 0.4798896504144996f;
__device__ __constant__ float cB4 = 1.379008574103742f;
__device__ __constant__ float cB5 = -3.290069515436081f;
__device__ __constant__ float cB6 = 2.324710524099774f;

struct BiasReg {
    float b1a, b1b;       // b1[lane], b1[lane+32]
    float b2a, b2b;       // b2[lane], b2[lane+32]
    float b30, b31, b32;  // b3[3*lane + {0,1,2}]
};

__device__ __forceinline__ float fast_tanh(float x) {
    // tanh(x) = 1 - 2/(exp(2x)+1); branch-free, saturates correctly at +/-inf
    float e = __expf(2.0f * x);
    return 1.0f - __fdividef(2.0f, e + 1.0f);
}

// One vector-field evaluation for NB batch elements held by this warp.
// zs[nb] : this lane's component of the stage input (lane h owns element h)
// dq[nb][c] : per-batch control increment (uniform across lanes)
// kout[nb] : this lane's component of the CDE increment
__device__ __forceinline__ void vf_eval(
    const float* __restrict__ sw1,
    const float* __restrict__ sw2,
    const float* __restrict__ sw3,
    const BiasReg& bias, int lane,
    const float zs[NB], const float dq[NB][CINC], float kout[NB])
{
    const unsigned FULL = 0xffffffffu;

    // ---- Layer 1: (32 -> 64), lane computes outputs lane and lane+32 ----
    float a0[NB], a1[NB];
#pragma unroll
    for (int nb = 0; nb < NB; nb++) { a0[nb] = bias.b1a; a1[nb] = bias.b1b; }
#pragma unroll 4
    for (int h = 0; h < HD; h++) {
        float wa = sw1[(lane << 5) + (h ^ lane)];
        float wb = sw1[((lane + 32) << 5) + (h ^ lane)];
#pragma unroll
        for (int nb = 0; nb < NB; nb++) {
            float zb = __shfl_sync(FULL, zs[nb], h);
            a0[nb] = fmaf(wa, zb, a0[nb]);
            a1[nb] = fmaf(wb, zb, a1[nb]);
        }
    }
    float h1lo[NB], h1hi[NB];
#pragma unroll
    for (int nb = 0; nb < NB; nb++) {
        h1lo[nb] = fast_tanh(a0[nb]);
        h1hi[nb] = fast_tanh(a1[nb]);
    }

    // ---- Layer 2: (64 -> 64) ----
    float c0[NB], c1[NB];
#pragma unroll
    for (int nb = 0; nb < NB; nb++) { c0[nb] = bias.b2a; c1[nb] = bias.b2b; }
#pragma unroll 4
    for (int h = 0; h < 32; h++) {
        float wa = sw2[(lane << 6) + (h ^ lane)];
        float wb = sw2[((lane + 32) << 6) + (h ^ lane)];
#pragma unroll
        for (int nb = 0; nb < NB; nb++) {
            float hb = __shfl_sync(FULL, h1lo[nb], h);
            c0[nb] = fmaf(wa, hb, c0[nb]);
            c1[nb] = fmaf(wb, hb, c1[nb]);
        }
    }
#pragma unroll 4
    for (int h = 0; h < 32; h++) {
        float wa = sw2[(lane << 6) + ((h + 32) ^ lane)];
        float wb = sw2[((lane + 32) << 6) + ((h + 32) ^ lane)];
#pragma unroll
        for (int nb = 0; nb < NB; nb++) {
            float hb = __shfl_sync(FULL, h1hi[nb], h);
            c0[nb] = fmaf(wa, hb, c0[nb]);
            c1[nb] = fmaf(wb, hb, c1[nb]);
        }
    }
    float h2lo[NB], h2hi[NB];
#pragma unroll
    for (int nb = 0; nb < NB; nb++) {
        h2lo[nb] = fast_tanh(c0[nb]);
        h2hi[nb] = fast_tanh(c1[nb]);
    }

    // ---- Layer 3: (64 -> 96), lane computes rows 3*lane + {0,1,2} ----
    float f0[NB], f1[NB], f2[NB];
#pragma unroll
    for (int nb = 0; nb < NB; nb++) { f0[nb] = bias.b30; f1[nb] = bias.b31; f2[nb] = bias.b32; }
    int r0 = 3 * lane;
    int k0 = r0 & 31, k1r = (r0 + 1) & 31, k2r = (r0 + 2) & 31;
#pragma unroll 4
    for (int h = 0; h < 32; h++) {
        float w0 = sw3[(r0 << 6) + (h ^ k0)];
        float w1v = sw3[((r0 + 1) << 6) + (h ^ k1r)];
        float w2v = sw3[((r0 + 2) << 6) + (h ^ k2r)];
#pragma unroll
        for (int nb = 0; nb < NB; nb++) {
            float hb = __shfl_sync(FULL, h2lo[nb], h);
            f0[nb] = fmaf(w0, hb, f0[nb]);
            f1[nb] = fmaf(w1v, hb, f1[nb]);
            f2[nb] = fmaf(w2v, hb, f2[nb]);
        }
    }
#pragma unroll 4
    for (int h = 0; h < 32; h++) {
        float w0 = sw3[(r0 << 6) + ((h + 32) ^ k0)];
        float w1v = sw3[((r0 + 1) << 6) + ((h + 32) ^ k1r)];
        float w2v = sw3[((r0 + 2) << 6) + ((h + 32) ^ k2r)];
#pragma unroll
        for (int nb = 0; nb < NB; nb++) {
            float hb = __shfl_sync(FULL, h2hi[nb], h);
            f0[nb] = fmaf(w0, hb, f0[nb]);
            f1[nb] = fmaf(w1v, hb, f1[nb]);
            f2[nb] = fmaf(w2v, hb, f2[nb]);
        }
    }

    // ---- Contract with dq: k[h] = f[h,:] . dq ----
#pragma unroll
    for (int nb = 0; nb < NB; nb++) {
        float k = f0[nb] * dq[nb][0];
        k = fmaf(f1[nb], dq[nb][1], k);
        k = fmaf(f2[nb], dq[nb][2], k);
        kout[nb] = k;
    }
}

__global__ __launch_bounds__(256, 2) void cde_kernel(
    const float* __restrict__ times,
    const float* __restrict__ grads,  // (B, T, 3)
    const float* __restrict__ w1, const float* __restrict__ b1,
    const float* __restrict__ w2, const float* __restrict__ b2,
    const float* __restrict__ w3, const float* __restrict__ b3,
    const float* __restrict__ w_enc, const float* __restrict__ b_enc,
    const float* __restrict__ w_ro, const float* __restrict__ b_ro,
    float* __restrict__ out, int B, int T)
{
    // XOR-swizzled weight tiles: exactly 48 KB static shared
    __shared__ float sw1[WIDF * HD];          // 8192 B
    __shared__ float sw2[WIDF * WIDF];        // 16384 B
    __shared__ float sw3[HD * CINC * WIDF];   // 24576 B

    int tid = threadIdx.x;
    for (int i = tid; i < WIDF * HD; i += blockDim.x) {
        int r = i >> 5, c = i & 31;
        sw1[(r << 5) + (c ^ (r & 31))] = w1[i];
    }
    for (int i = tid; i < WIDF * WIDF; i += blockDim.x) {
        int r = i >> 6, c = i & 63;
        sw2[(r << 6) + (c ^ (r & 31))] = w2[i];
    }
    for (int i = tid; i < HD * CINC * WIDF; i += blockDim.x) {
        int r = i >> 6, c = i & 63;
        sw3[(r << 6) + (c ^ (r & 31))] = w3[i];
    }
    __syncthreads();

    int lane = tid & 31;
    int warp_global = blockIdx.x * (blockDim.x >> 5) + (tid >> 5);
    int bbase = warp_global * NB;
    if (bbase >= B) return;

    // Biases in registers (per-lane slices)
    BiasReg bias;
    bias.b1a = b1[lane]; bias.b1b = b1[lane + 32];
    bias.b2a = b2[lane]; bias.b2b = b2[lane + 32];
    bias.b30 = b3[3 * lane + 0]; bias.b31 = b3[3 * lane + 1]; bias.b32 = b3[3 * lane + 2];

    float dt = times[1] - times[0];

    // z0 = encoder([1.0]) = w_enc[:,0] + b_enc — identical for all batches
    float z[NB];
    {
        float z0 = w_enc[lane] + b_enc[lane];
#pragma unroll
        for (int nb = 0; nb < NB; nb++) z[nb] = z0;
    }

    // Per-batch gradient base pointers (clamped for safety)
    const float* gp[NB];
#pragma unroll
    for (int nb = 0; nb < NB; nb++) {
        int bb = bbase + nb; if (bb >= B) bb = B - 1;
        gp[nb] = grads + (size_t)bb * (size_t)T * CINC;
    }

    float k1[NB], k2[NB], k3[NB], k4[NB], k5[NB], k6[NB], zs[NB];
    float dq[NB][CINC];

    for (int n = 0; n < T - 1; n++) {
        // dq_n = dt * gradients[:, n, :]  (cumsum/shift/diff telescopes exactly)
#pragma unroll
        for (int nb = 0; nb < NB; nb++) {
            const float* g = gp[nb] + n * CINC;
            dq[nb][0] = g[0] * dt;
            dq[nb][1] = g[1] * dt;
            dq[nb][2] = g[2] * dt;
        }

        vf_eval(sw1, sw2, sw3, bias, lane, z, dq, k1);

#pragma unroll
        for (int nb = 0; nb < NB; nb++) zs[nb] = fmaf(cA21, k1[nb], z[nb]);
        vf_eval(sw1, sw2, sw3, bias, lane, zs, dq, k2);

#pragma unroll
        for (int nb = 0; nb < NB; nb++)
            zs[nb] = fmaf(cA32, k2[nb], fmaf(cA31, k1[nb], z[nb]));
        vf_eval(sw1, sw2, sw3, bias, lane, zs, dq, k3);

#pragma unroll
        for (int nb = 0; nb < NB; nb++)
            zs[nb] = fmaf(cA43, k3[nb], fmaf(cA42, k2[nb], fmaf(cA41, k1[nb], z[nb])));
        vf_eval(sw1, sw2, sw3, bias, lane, zs, dq, k4);

#pragma unroll
        for (int nb = 0; nb < NB; nb++)
            zs[nb] = fmaf(cA54, k4[nb], fmaf(cA53, k3[nb], fmaf(cA52, k2[nb], fmaf(cA51, k1[nb], z[nb]))));
        vf_eval(sw1, sw2, sw3, bias, lane, zs, dq, k5);

#pragma unroll
        for (int nb = 0; nb < NB; nb++)
            zs[nb] = fmaf(cA65, k5[nb], fmaf(cA64, k4[nb], fmaf(cA63, k3[nb],
                     fmaf(cA62, k2[nb], fmaf(cA61, k1[nb], z[nb])))));
        vf_eval(sw1, sw2, sw3, bias, lane, zs, dq, k6);

#pragma unroll
        for (int nb = 0; nb < NB; nb++)
            z[nb] = fmaf(cB6, k6[nb], fmaf(cB5, k5[nb], fmaf(cB4, k4[nb],
                    fmaf(cB3, k3[nb], fmaf(cB2, k2[nb], fmaf(cB1, k1[nb], z[nb]))))));
    }

    // Readout: sigmoid(z . w_ro + b_ro)
    float wro = w_ro[lane];
    float br0 = b_ro[0];
#pragma unroll
    for (int nb = 0; nb < NB; nb++) {
        float v = z[nb] * wro;
#pragma unroll
        for (int off = 16; off > 0; off >>= 1)
            v += __shfl_xor_sync(0xffffffffu, v, off);
        if (lane == 0 && bbase + nb < B) {
            float logit = v + br0;
            out[bbase + nb] = __fdividef(1.0f, 1.0f + __expf(-logit));
        }
    }
}

extern "C" void kernel_launch(void* const* d_in, const int* in_sizes, int n_in,
                              void* d_out, int out_size) {
    const float* times = (const float*)d_in[0];
    const float* grads = (const float*)d_in[1];
    const float* w1    = (const float*)d_in[2];
    const float* b1    = (const float*)d_in[3];
    const float* w2    = (const float*)d_in[4];
    const float* b2    = (const float*)d_in[5];
    const float* w3    = (const float*)d_in[6];
    const float* b3    = (const float*)d_in[7];
    const float* w_enc = (const float*)d_in[8];
    const float* b_enc = (const float*)d_in[9];
    const float* w_ro  = (const float*)d_in[10];
    const float* b_ro  = (const float*)d_in[11];
    float* out = (float*)d_out;

    int T = in_sizes[0];
    int B = in_sizes[1] / (T * CINC);

    int warps = (B + NB - 1) / NB;
    int threads = 256;
    int blocks = (warps * 32 + threads - 1) / threads;
    cde_kernel<<<blocks, threads>>>(times, grads, w1, b1, w2, b2, w3, b3,
                                    w_enc, b_enc, w_ro, b_ro, out, B, T);
}

// round 2
// speedup vs baseline: 2.1294x; 2.1294x over previous
#include <cuda_runtime.h>
#include <cstddef>

#define NB    8     // batches per warp (4 packed f32x2 pairs)
#define NPAIR 4
#define HD    32
#define WIDF  64
#define CINC  3

// Padded smem strides (floats): conflict-free, immediate-offset addressing
#define S1 36
#define S2 68
#define S3 68
#define OFF2 (64 * S1)               // 2304
#define OFF3 (OFF2 + 64 * S2)        // 6656
#define ACT_OFF (OFF3 + 96 * S3)     // 13184
#define ACT_PER_WARP (NPAIR * 96 * 2)  // 768 floats (pairs x 96 x 2)
#define WARPS_PER_CTA 4
#define SMEM_FLOATS (ACT_OFF + WARPS_PER_CTA * ACT_PER_WARP)  // 16256 -> 65024 B

typedef unsigned long long u64;

__device__ __forceinline__ u64 pk(float lo, float hi) {
    u64 r; asm("mov.b64 %0, {%1, %2};" : "=l"(r) : "f"(lo), "f"(hi)); return r;
}
__device__ __forceinline__ void upk(float& lo, float& hi, u64 v) {
    asm("mov.b64 {%0, %1}, %2;" : "=f"(lo), "=f"(hi) : "l"(v));
}
__device__ __forceinline__ u64 fma2(u64 a, u64 b, u64 c) {
    u64 d; asm("fma.rn.f32x2 %0, %1, %2, %3;" : "=l"(d) : "l"(a), "l"(b), "l"(c)); return d;
}
__device__ __forceinline__ u64 mul2(u64 a, u64 b) {
    u64 d; asm("mul.rn.f32x2 %0, %1, %2;" : "=l"(d) : "l"(a), "l"(b)); return d;
}
__device__ __forceinline__ float fast_tanh(float x) {
    float e = __expf(2.0f * x);
    return 1.0f - __fdividef(2.0f, e + 1.0f);
}

__global__ void __launch_bounds__(128, 3) cde_kernel(
    const float* __restrict__ times,
    const float* __restrict__ grads,  // (B, T, 3)
    const float* __restrict__ w1, const float* __restrict__ b1,
    const float* __restrict__ w2, const float* __restrict__ b2,
    const float* __restrict__ w3, const float* __restrict__ b3,
    const float* __restrict__ w_enc, const float* __restrict__ b_enc,
    const float* __restrict__ w_ro, const float* __restrict__ b_ro,
    float* __restrict__ out, int B, int T)
{
    extern __shared__ float smem[];
    int tid = threadIdx.x;

    // Load weights into padded-stride smem (no swizzle -> immediate addressing)
    for (int i = tid; i < 64 * 32; i += 128) smem[(i >> 5) * S1 + (i & 31)] = w1[i];
    for (int i = tid; i < 64 * 64; i += 128) smem[OFF2 + (i >> 6) * S2 + (i & 63)] = w2[i];
    for (int i = tid; i < 96 * 64; i += 128) smem[OFF3 + (i >> 6) * S3 + (i & 63)] = w3[i];
    __syncthreads();

    int lane = tid & 31;
    int wid = tid >> 5;
    int wbase = (blockIdx.x * WARPS_PER_CTA + wid) * NB;
    if (wbase >= B) return;

    float* actw = smem + ACT_OFF + wid * ACT_PER_WARP;
    float2* actp = (float2*)actw;

    const float* w1a = smem + lane * S1;
    const float* w1b = smem + (lane + 32) * S1;
    const float* w2a = smem + OFF2 + lane * S2;
    const float* w2b = smem + OFF2 + (lane + 32) * S2;
    const float* w3a = smem + OFF3 + (3 * lane) * S3;
    const float* w3b = w3a + S3;
    const float* w3c = w3b + S3;

    // Packed biases
    u64 pb1a = pk(b1[lane], b1[lane]);
    u64 pb1b = pk(b1[lane + 32], b1[lane + 32]);
    u64 pb2a = pk(b2[lane], b2[lane]);
    u64 pb2b = pk(b2[lane + 32], b2[lane + 32]);
    u64 pb3a = pk(b3[3 * lane + 0], b3[3 * lane + 0]);
    u64 pb3b = pk(b3[3 * lane + 1], b3[3 * lane + 1]);
    u64 pb3c = pk(b3[3 * lane + 2], b3[3 * lane + 2]);

    float dt = times[1] - times[0];
    float z[NB];
    {
        float z0 = w_enc[lane] + b_enc[lane];
#pragma unroll
        for (int i = 0; i < NB; i++) z[i] = z0;
    }

    const float* gbase = grads + (size_t)wbase * (size_t)T * CINC;
    const size_t bstride = (size_t)T * CINC;

    float k1[NB], k2[NB], k3[NB], k4[NB], k5[NB], zsv[NB], kc[NB];

#pragma unroll 1
    for (int n = 0; n < T - 1; n++) {
        // dq_n = dt * gradients[:, n, :]
        u64 dq0[NPAIR], dq1[NPAIR], dq2[NPAIR];
#pragma unroll
        for (int p = 0; p < NPAIR; p++) {
            const float* gA = gbase + (size_t)(2 * p) * bstride + (size_t)n * CINC;
            const float* gB = gA + bstride;
            dq0[p] = pk(gA[0] * dt, gB[0] * dt);
            dq1[p] = pk(gA[1] * dt, gB[1] * dt);
            dq2[p] = pk(gA[2] * dt, gB[2] * dt);
        }

#pragma unroll
        for (int i = 0; i < NB; i++) zsv[i] = z[i];

#pragma unroll 1
        for (int s = 0; s < 6; s++) {
            // Broadcast stage input to smem, paired layout [pair][h][2]
#pragma unroll
            for (int p = 0; p < NPAIR; p++)
                actp[p * 96 + lane] = make_float2(zsv[2 * p], zsv[2 * p + 1]);
            __syncwarp();

            // ---- Layer 1: 32 -> 64 ----
            u64 a0[NPAIR], a1[NPAIR];
#pragma unroll
            for (int p = 0; p < NPAIR; p++) { a0[p] = pb1a; a1[p] = pb1b; }
#pragma unroll 4
            for (int hg = 0; hg < 8; hg++) {
                float4 wa = *(const float4*)(w1a + hg * 4);
                float4 wb = *(const float4*)(w1b + hg * 4);
                u64 wa0 = pk(wa.x, wa.x), wa1 = pk(wa.y, wa.y), wa2 = pk(wa.z, wa.z), wa3 = pk(wa.w, wa.w);
                u64 wb0 = pk(wb.x, wb.x), wb1 = pk(wb.y, wb.y), wb2 = pk(wb.z, wb.z), wb3 = pk(wb.w, wb.w);
#pragma unroll
                for (int p = 0; p < NPAIR; p++) {
                    ulonglong2 A = *(const ulonglong2*)(actw + p * 192 + hg * 8);
                    ulonglong2 Bv = *(const ulonglong2*)(actw + p * 192 + hg * 8 + 4);
                    a0[p] = fma2(wa0, A.x, a0[p]);  a0[p] = fma2(wa1, A.y, a0[p]);
                    a0[p] = fma2(wa2, Bv.x, a0[p]); a0[p] = fma2(wa3, Bv.y, a0[p]);
                    a1[p] = fma2(wb0, A.x, a1[p]);  a1[p] = fma2(wb1, A.y, a1[p]);
                    a1[p] = fma2(wb2, Bv.x, a1[p]); a1[p] = fma2(wb3, Bv.y, a1[p]);
                }
            }
#pragma unroll
            for (int p = 0; p < NPAIR; p++) {
                float lo, hi;
                upk(lo, hi, a0[p]);
                actp[p * 96 + lane] = make_float2(fast_tanh(lo), fast_tanh(hi));
                upk(lo, hi, a1[p]);
                actp[p * 96 + lane + 32] = make_float2(fast_tanh(lo), fast_tanh(hi));
            }
            __syncwarp();

            // ---- Layer 2: 64 -> 64 ----
            u64 c0[NPAIR], c1[NPAIR];
#pragma unroll
            for (int p = 0; p < NPAIR; p++) { c0[p] = pb2a; c1[p] = pb2b; }
#pragma unroll 4
            for (int hg = 0; hg < 16; hg++) {
                float4 wa = *(const float4*)(w2a + hg * 4);
                float4 wb = *(const float4*)(w2b + hg * 4);
                u64 wa0 = pk(wa.x, wa.x), wa1 = pk(wa.y, wa.y), wa2 = pk(wa.z, wa.z), wa3 = pk(wa.w, wa.w);
                u64 wb0 = pk(wb.x, wb.x), wb1 = pk(wb.y, wb.y), wb2 = pk(wb.z, wb.z), wb3 = pk(wb.w, wb.w);
#pragma unroll
                for (int p = 0; p < NPAIR; p++) {
                    ulonglong2 A = *(const ulonglong2*)(actw + p * 192 + hg * 8);
                    ulonglong2 Bv = *(const ulonglong2*)(actw + p * 192 + hg * 8 + 4);
                    c0[p] = fma2(wa0, A.x, c0[p]);  c0[p] = fma2(wa1, A.y, c0[p]);
                    c0[p] = fma2(wa2, Bv.x, c0[p]); c0[p] = fma2(wa3, Bv.y, c0[p]);
                    c1[p] = fma2(wb0, A.x, c1[p]);  c1[p] = fma2(wb1, A.y, c1[p]);
                    c1[p] = fma2(wb2, Bv.x, c1[p]); c1[p] = fma2(wb3, Bv.y, c1[p]);
                }
            }
#pragma unroll
            for (int p = 0; p < NPAIR; p++) {
                float lo, hi;
                upk(lo, hi, c0[p]);
                actp[p * 96 + lane] = make_float2(fast_tanh(lo), fast_tanh(hi));
                upk(lo, hi, c1[p]);
                actp[p * 96 + lane + 32] = make_float2(fast_tanh(lo), fast_tanh(hi));
            }
            __syncwarp();

            // ---- Layer 3: 64 -> 96 (rows 3*lane + {0,1,2}) ----
            u64 f0[NPAIR], f1[NPAIR], f2[NPAIR];
#pragma unroll
            for (int p = 0; p < NPAIR; p++) { f0[p] = pb3a; f1[p] = pb3b; f2[p] = pb3c; }
#pragma unroll 4
            for (int hg = 0; hg < 16; hg++) {
                float4 wA = *(const float4*)(w3a + hg * 4);
                float4 wB = *(const float4*)(w3b + hg * 4);
                float4 wC = *(const float4*)(w3c + hg * 4);
                u64 wA0 = pk(wA.x, wA.x), wA1 = pk(wA.y, wA.y), wA2 = pk(wA.z, wA.z), wA3 = pk(wA.w, wA.w);
                u64 wB0 = pk(wB.x, wB.x), wB1 = pk(wB.y, wB.y), wB2 = pk(wB.z, wB.z), wB3 = pk(wB.w, wB.w);
                u64 wC0 = pk(wC.x, wC.x), wC1 = pk(wC.y, wC.y), wC2 = pk(wC.z, wC.z), wC3 = pk(wC.w, wC.w);
#pragma unroll
                for (int p = 0; p < NPAIR; p++) {
                    ulonglong2 A = *(const ulonglong2*)(actw + p * 192 + hg * 8);
                    ulonglong2 Bv = *(const ulonglong2*)(actw + p * 192 + hg * 8 + 4);
                    f0[p] = fma2(wA0, A.x, f0[p]);  f0[p] = fma2(wA1, A.y, f0[p]);
                    f0[p] = fma2(wA2, Bv.x, f0[p]); f0[p] = fma2(wA3, Bv.y, f0[p]);
                    f1[p] = fma2(wB0, A.x, f1[p]);  f1[p] = fma2(wB1, A.y, f1[p]);
                    f1[p] = fma2(wB2, Bv.x, f1[p]); f1[p] = fma2(wB3, Bv.y, f1[p]);
                    f2[p] = fma2(wC0, A.x, f2[p]);  f2[p] = fma2(wC1, A.y, f2[p]);
                    f2[p] = fma2(wC2, Bv.x, f2[p]); f2[p] = fma2(wC3, Bv.y, f2[p]);
                }
            }
            // Contract with dq (packed), unpack k
#pragma unroll
            for (int p = 0; p < NPAIR; p++) {
                u64 kk = mul2(f0[p], dq0[p]);
                kk = fma2(f1[p], dq1[p], kk);
                kk = fma2(f2[p], dq2[p], kk);
                upk(kc[2 * p], kc[2 * p + 1], kk);
            }

            // Tsit5 stage combine (scalar; FFMA-imm path)
            if (s == 0) {
#pragma unroll
                for (int i = 0; i < NB; i++) { k1[i] = kc[i]; zsv[i] = fmaf(0.161f, kc[i], z[i]); }
            } else if (s == 1) {
#pragma unroll
                for (int i = 0; i < NB; i++) {
                    k2[i] = kc[i];
                    zsv[i] = fmaf(0.335480655492357f, kc[i], fmaf(-0.008480655492356989f, k1[i], z[i]));
                }
            } else if (s == 2) {
#pragma unroll
                for (int i = 0; i < NB; i++) {
                    k3[i] = kc[i];
                    zsv[i] = fmaf(4.3622954328695815f, kc[i], fmaf(-6.359448489975075f, k2[i],
                             fmaf(2.8971530571054935f, k1[i], z[i])));
                }
            } else if (s == 3) {
#pragma unroll
                for (int i = 0; i < NB; i++) {
                    k4[i] = kc[i];
                    zsv[i] = fmaf(-0.09249506636175525f, kc[i], fmaf(7.4955393428898365f, k3[i],
                             fmaf(-11.748883564062828f, k2[i], fmaf(5.325864828439257f, k1[i], z[i]))));
                }
            } else if (s == 4) {
#pragma unroll
                for (int i = 0; i < NB; i++) {
                    k5[i] = kc[i];
                    zsv[i] = fmaf(-0.028269050394068383f, kc[i], fmaf(-0.071584973281401f, k4[i],
                             fmaf(8.159367898576159f, k3[i], fmaf(-12.92096931784711f, k2[i],
                             fmaf(5.86145544294642f, k1[i], z[i])))));
                }
            } else {
#pragma unroll
                for (int i = 0; i < NB; i++) {
                    z[i] = fmaf(2.324710524099774f, kc[i], fmaf(-3.290069515436081f, k5[i],
                           fmaf(1.379008574103742f, k4[i], fmaf(0.4798896504144996f, k3[i],
                           fmaf(0.01f, k2[i], fmaf(0.09646076681806523f, k1[i], z[i]))))));
                }
            }
        }
    }

    // Readout: sigmoid(z . w_ro + b_ro)
    float wro = w_ro[lane];
    float br0 = b_ro[0];
#pragma unroll
    for (int nb = 0; nb < NB; nb++) {
        float v = z[nb] * wro;
#pragma unroll
        for (int off = 16; off > 0; off >>= 1)
            v += __shfl_xor_sync(0xffffffffu, v, off);
        if (lane == 0 && wbase + nb < B) {
            float logit = v + br0;
            out[wbase + nb] = __fdividef(1.0f, 1.0f + __expf(-logit));
        }
    }
}

extern "C" void kernel_launch(void* const* d_in, const int* in_sizes, int n_in,
                              void* d_out, int out_size) {
    const float* times = (const float*)d_in[0];
    const float* grads = (const float*)d_in[1];
    const float* w1    = (const float*)d_in[2];
    const float* b1    = (const float*)d_in[3];
    const float* w2    = (const float*)d_in[4];
    const float* b2    = (const float*)d_in[5];
    const float* w3    = (const float*)d_in[6];
    const float* b3    = (const float*)d_in[7];
    const float* w_enc = (const float*)d_in[8];
    const float* b_enc = (const float*)d_in[9];
    const float* w_ro  = (const float*)d_in[10];
    const float* b_ro  = (const float*)d_in[11];
    float* out = (float*)d_out;

    int T = in_sizes[0];
    int B = in_sizes[1] / (T * CINC);

    size_t smem_bytes = SMEM_FLOATS * sizeof(float);  // 65024
    cudaFuncSetAttribute(cde_kernel, cudaFuncAttributeMaxDynamicSharedMemorySize,
                         (int)smem_bytes);

    int batches_per_cta = WARPS_PER_CTA * NB;  // 32
    int blocks = (B + batches_per_cta - 1) / batches_per_cta;  // 512
    cde_kernel<<<blocks, 128, smem_bytes>>>(times, grads, w1, b1, w2, b2, w3, b3,
                                            w_enc, b_enc, w_ro, b_ro, out, B, T);
}

// round 5
// speedup vs baseline: 3.3812x; 1.5879x over previous
#include <cuda_runtime.h>
#include <cstdint>
#include <cstddef>

#define CINC  3
#define WARPS 4
#define MB    16               // batches per warp (one m16 tile)
#define CTAB  (WARPS * MB)     // 64
#define NTH   (WARPS * 32)

// ---- smem layout (bytes) ----
// B-fragments: per (plane, ntile, ktile): 32 lanes x uint2 (b0,b1) = 256B
#define BF1_OFF 0              // 3*8*2*256  = 12288
#define BF2_OFF 12288          // 3*8*4*256  = 24576
#define BF3_OFF 36864          // 3*12*4*256 = 36864
#define B1E_OFF 73728          // 8*32*8 = 2048
#define B2E_OFF 75776          // 2048
#define B3E_OFF 77824          // 12*32*8 = 3072
#define SMEM_BYTES 80896

__device__ __forceinline__ float hi16f(uint32_t u) { return __uint_as_float(u & 0xFFFF0000u); }

// bf16 (top-16-bits) of plane p of the 3-way truncation split of v, as low 16 bits
__device__ __forceinline__ uint32_t bf_plane(float v, int p) {
    uint32_t u = __float_as_uint(v);
    if (p == 0) return u >> 16;
    float r = v - hi16f(u);
    uint32_t ur = __float_as_uint(r);
    if (p == 1) return ur >> 16;
    float r2 = r - hi16f(ur);
    return __float_as_uint(r2) >> 16;
}

// split two fp32 into packed bf16x2 words for 3 planes (low half = first value)
__device__ __forceinline__ void split_pair(float va, float vb,
                                           uint32_t& p0, uint32_t& p1, uint32_t& p2) {
    uint32_t Aa = __float_as_uint(va), Ab = __float_as_uint(vb);
    float ra = va - hi16f(Aa), rb = vb - hi16f(Ab);
    uint32_t Ra = __float_as_uint(ra), Rb = __float_as_uint(rb);
    float sa = ra - hi16f(Ra), sb = rb - hi16f(Rb);
    uint32_t Sa = __float_as_uint(sa), Sb = __float_as_uint(sb);
    p0 = __byte_perm(Aa, Ab, 0x7632);
    p1 = __byte_perm(Ra, Rb, 0x7632);
    p2 = __byte_perm(Sa, Sb, 0x7632);
}

__device__ __forceinline__ float fast_tanh(float x) {
    float e = __expf(2.0f * x);
    return 1.0f - __fdividef(2.0f, e + 1.0f);
}

__device__ __forceinline__ void mma_bf16(float* d, const uint32_t* a, uint32_t b0, uint32_t b1) {
    asm volatile("mma.sync.aligned.m16n8k16.row.col.f32.bf16.bf16.f32 "
                 "{%0,%1,%2,%3}, {%4,%5,%6,%7}, {%8,%9}, {%0,%1,%2,%3};"
                 : "+f"(d[0]), "+f"(d[1]), "+f"(d[2]), "+f"(d[3])
                 : "r"(a[0]), "r"(a[1]), "r"(a[2]), "r"(a[3]), "r"(b0), "r"(b1));
}

// One split-GEMM layer: D[NT][4] = bias + sum of 6 bf16 products of A (3 planes) x B (3 planes).
// B loaded once per (pb, kt, nt), reused across the A-planes paired with it:
//   pb=0: pa 0,1,2 ; pb=1: pa 0,1 ; pb=2: pa 0   (errors beyond ~2^-24 dropped)
template<int NT, int KT>
__device__ __forceinline__ void run_gemm(float (*D)[4], const uint2* frags,
                                         const float2* biasE,
                                         const uint32_t A[3][4][4], int lane) {
#pragma unroll
    for (int nt = 0; nt < NT; nt++) {
        float2 bb = biasE[nt * 32 + lane];
        D[nt][0] = bb.x; D[nt][1] = bb.y; D[nt][2] = bb.x; D[nt][3] = bb.y;
    }
#pragma unroll
    for (int pb = 0; pb < 3; pb++) {
#pragma unroll
        for (int kt = 0; kt < KT; kt++) {
#pragma unroll
            for (int nt = 0; nt < NT; nt++) {
                uint2 Bv = frags[((pb * NT + nt) * KT + kt) * 32 + lane];
                mma_bf16(D[nt], A[0][kt], Bv.x, Bv.y);
                if (pb < 2) mma_bf16(D[nt], A[1][kt], Bv.x, Bv.y);
                if (pb == 0) mma_bf16(D[nt], A[2][kt], Bv.x, Bv.y);
            }
        }
    }
}

// Epilogue for an 8-ntile layer: tanh(D) -> 3-plane A fragments (ktile q from ntiles 2q,2q+1)
__device__ __forceinline__ void epilogue_tanh(const float (*D)[4], uint32_t A[3][4][4]) {
#pragma unroll
    for (int q = 0; q < 4; q++) {
        float t0 = fast_tanh(D[2 * q][0]), t1 = fast_tanh(D[2 * q][1]);
        split_pair(t0, t1, A[0][q][0], A[1][q][0], A[2][q][0]);
        t0 = fast_tanh(D[2 * q][2]); t1 = fast_tanh(D[2 * q][3]);
        split_pair(t0, t1, A[0][q][1], A[1][q][1], A[2][q][1]);
        t0 = fast_tanh(D[2 * q + 1][0]); t1 = fast_tanh(D[2 * q + 1][1]);
        split_pair(t0, t1, A[0][q][2], A[1][q][2], A[2][q][2]);
        t0 = fast_tanh(D[2 * q + 1][2]); t1 = fast_tanh(D[2 * q + 1][3]);
        split_pair(t0, t1, A[0][q][3], A[1][q][3], A[2][q][3]);
    }
}

__global__ void __launch_bounds__(NTH, 2) cde_hmma_kernel(
    const float* __restrict__ times,
    const float* __restrict__ grads,
    const float* __restrict__ w1, const float* __restrict__ b1,
    const float* __restrict__ w2, const float* __restrict__ b2,
    const float* __restrict__ w3, const float* __restrict__ b3,
    const float* __restrict__ w_enc, const float* __restrict__ b_enc,
    const float* __restrict__ w_ro, const float* __restrict__ b_ro,
    float* __restrict__ out, int B, int T)
{
    extern __shared__ char sm[];
    int tid = threadIdx.x;
    int lane = tid & 31, warp = tid >> 5;

    // ---- Build B-fragment planes + expanded biases in smem ----
    // Layer1: W1 64x32
    for (int idx = tid; idx < 3 * 8 * 2 * 32; idx += NTH) {
        int ln = idx & 31, f = idx >> 5;
        int kt = f % 2, nt = (f / 2) % 8, p = f / 16;
        int n = nt * 8 + ln / 4, k0 = kt * 16 + 2 * (ln & 3);
        const float* wr = w1 + n * 32;
        uint32_t l0 = bf_plane(wr[k0], p),     l1 = bf_plane(wr[k0 + 1], p);
        uint32_t h0 = bf_plane(wr[k0 + 8], p), h1 = bf_plane(wr[k0 + 9], p);
        ((uint2*)(sm + BF1_OFF))[f * 32 + ln] = make_uint2(l0 | (l1 << 16), h0 | (h1 << 16));
    }
    // Layer2: W2 64x64
    for (int idx = tid; idx < 3 * 8 * 4 * 32; idx += NTH) {
        int ln = idx & 31, f = idx >> 5;
        int kt = f % 4, nt = (f / 4) % 8, p = f / 32;
        int n = nt * 8 + ln / 4, k0 = kt * 16 + 2 * (ln & 3);
        const float* wr = w2 + n * 64;
        uint32_t l0 = bf_plane(wr[k0], p),     l1 = bf_plane(wr[k0 + 1], p);
        uint32_t h0 = bf_plane(wr[k0 + 8], p), h1 = bf_plane(wr[k0 + 9], p);
        ((uint2*)(sm + BF2_OFF))[f * 32 + ln] = make_uint2(l0 | (l1 << 16), h0 | (h1 << 16));
    }
    // Layer3: W3 96x64, rows PERMUTED: logical n' = h + 32*ch  <-  original row 3h+ch
    for (int idx = tid; idx < 3 * 12 * 4 * 32; idx += NTH) {
        int ln = idx & 31, f = idx >> 5;
        int kt = f % 4, nt = (f / 4) % 12, p = f / 48;
        int np = nt * 8 + ln / 4;                 // logical col 0..95
        int row = 3 * (np & 31) + (np >> 5);      // original W3 row
        int k0 = kt * 16 + 2 * (ln & 3);
        const float* wr = w3 + row * 64;
        uint32_t l0 = bf_plane(wr[k0], p),     l1 = bf_plane(wr[k0 + 1], p);
        uint32_t h0 = bf_plane(wr[k0 + 8], p), h1 = bf_plane(wr[k0 + 9], p);
        ((uint2*)(sm + BF3_OFF))[f * 32 + ln] = make_uint2(l0 | (l1 << 16), h0 | (h1 << 16));
    }
    // Expanded biases: biasE[nt*32+lane] = {b[8nt+2(l%4)], b[8nt+2(l%4)+1]}
    for (int idx = tid; idx < 8 * 32; idx += NTH) {
        int ln = idx & 31, nt = idx >> 5;
        int c = 8 * nt + 2 * (ln & 3);
        ((float2*)(sm + B1E_OFF))[idx] = make_float2(b1[c], b1[c + 1]);
        ((float2*)(sm + B2E_OFF))[idx] = make_float2(b2[c], b2[c + 1]);
    }
    for (int idx = tid; idx < 12 * 32; idx += NTH) {
        int ln = idx & 31, nt = idx >> 5;
        int c = 8 * nt + 2 * (ln & 3);                 // logical n'
        int i0 = 3 * (c & 31) + (c >> 5);              // original b3 idx
        int c1v = c + 1;
        int i1 = 3 * (c1v & 31) + (c1v >> 5);
        ((float2*)(sm + B3E_OFF))[idx] = make_float2(b3[i0], b3[i1]);
    }
    __syncthreads();

    const uint2* bf1 = (const uint2*)(sm + BF1_OFF);
    const uint2* bf2 = (const uint2*)(sm + BF2_OFF);
    const uint2* bf3 = (const uint2*)(sm + BF3_OFF);
    const float2* be1 = (const float2*)(sm + B1E_OFF);
    const float2* be2 = (const float2*)(sm + B2E_OFF);
    const float2* be3 = (const float2*)(sm + B3E_OFF);

    // ---- per-warp batch rows ----
    int base = blockIdx.x * CTAB + warp * MB;
    int bA = base + (lane >> 2);          // rows l/4      (c0,c1)
    int bB = bA + 8;                      // rows l/4 + 8  (c2,c3)
    bool vA = bA < B, vB = bB < B;
    const float* gA = grads + (size_t)(vA ? bA : 0) * (size_t)T * CINC;
    const float* gB = grads + (size_t)(vB ? bB : 0) * (size_t)T * CINC;

    float dt = times[1] - times[0];

    // ---- state in D-fragment layout: elem (t,c): col = 8t+2(l%4)+(c&1), row per c ----
    float z[16], k1[16], k2[16], k3[16], k4[16], k5[16], zs[16];
#pragma unroll
    for (int t = 0; t < 4; t++) {
        int c = 8 * t + 2 * (lane & 3);
        float v0 = w_enc[c] + b_enc[c];
        float v1 = w_enc[c + 1] + b_enc[c + 1];
        z[t * 4 + 0] = v0; z[t * 4 + 1] = v1; z[t * 4 + 2] = v0; z[t * 4 + 3] = v1;
    }

    uint32_t As[3][4][4], An[3][4][4];   // ping-pong A fragments

#pragma unroll 1
    for (int n = 0; n < T - 1; n++) {
        float dqA[3], dqB[3];
#pragma unroll
        for (int c = 0; c < 3; c++) {
            dqA[c] = gA[n * 3 + c] * dt;
            dqB[c] = gB[n * 3 + c] * dt;
        }

#pragma unroll
        for (int i = 0; i < 16; i++) zs[i] = z[i];

#pragma unroll 1
        for (int s = 0; s < 6; s++) {
            // build A1 (K=32 -> ktiles 0,1) from zs; slots map D-frag -> A-frag locally
#pragma unroll
            for (int j = 0; j < 2; j++) {
                split_pair(zs[(2 * j) * 4 + 0], zs[(2 * j) * 4 + 1], As[0][j][0], As[1][j][0], As[2][j][0]);
                split_pair(zs[(2 * j) * 4 + 2], zs[(2 * j) * 4 + 3], As[0][j][1], As[1][j][1], As[2][j][1]);
                split_pair(zs[(2 * j + 1) * 4 + 0], zs[(2 * j + 1) * 4 + 1], As[0][j][2], As[1][j][2], As[2][j][2]);
                split_pair(zs[(2 * j + 1) * 4 + 2], zs[(2 * j + 1) * 4 + 3], As[0][j][3], As[1][j][3], As[2][j][3]);
            }

            // ---- GEMM1: (16x32)@W1^T -> 16x64 ----
            {
                float D[8][4];
                run_gemm<8, 2>(D, bf1, be1, As, lane);
                epilogue_tanh(D, An);
            }
            // ---- GEMM2: (16x64)@W2^T -> 16x64 ----
            {
                float D[8][4];
                run_gemm<8, 4>(D, bf2, be2, An, lane);
                epilogue_tanh(D, As);
            }
            // ---- GEMM3: (16x64)@W3p^T -> 16x96 (grouped; contract with dq per channel) ----
            float kc[4][4];
#pragma unroll
            for (int g = 0; g < 3; g++) {
                float D[4][4];
#pragma unroll
                for (int i = 0; i < 4; i++) {
                    float2 bb = be3[(g * 4 + i) * 32 + lane];
                    D[i][0] = bb.x; D[i][1] = bb.y; D[i][2] = bb.x; D[i][3] = bb.y;
                }
#pragma unroll
                for (int pb = 0; pb < 3; pb++) {
#pragma unroll
                    for (int kt = 0; kt < 4; kt++) {
#pragma unroll
                        for (int i = 0; i < 4; i++) {
                            uint2 Bv = bf3[((pb * 12 + g * 4 + i) * 4 + kt) * 32 + lane];
                            mma_bf16(D[i], As[0][kt], Bv.x, Bv.y);
                            if (pb < 2) mma_bf16(D[i], As[1][kt], Bv.x, Bv.y);
                            if (pb == 0) mma_bf16(D[i], As[2][kt], Bv.x, Bv.y);
                        }
                    }
                }
                float dA = dqA[g], dB = dqB[g];
                if (g == 0) {
#pragma unroll
                    for (int i = 0; i < 4; i++) {
                        kc[i][0] = D[i][0] * dA; kc[i][1] = D[i][1] * dA;
                        kc[i][2] = D[i][2] * dB; kc[i][3] = D[i][3] * dB;
                    }
                } else {
#pragma unroll
                    for (int i = 0; i < 4; i++) {
                        kc[i][0] = fmaf(D[i][0], dA, kc[i][0]); kc[i][1] = fmaf(D[i][1], dA, kc[i][1]);
                        kc[i][2] = fmaf(D[i][2], dB, kc[i][2]); kc[i][3] = fmaf(D[i][3], dB, kc[i][3]);
                    }
                }
            }
            float* kcf = &kc[0][0];

            // ---- Tsit5 stage combine ----
            if (s == 0) {
#pragma unroll
                for (int i = 0; i < 16; i++) { k1[i] = kcf[i]; zs[i] = fmaf(0.161f, kcf[i], z[i]); }
            } else if (s == 1) {
#pragma unroll
                for (int i = 0; i < 16; i++) {
                    k2[i] = kcf[i];
                    zs[i] = fmaf(0.335480655492357f, kcf[i], fmaf(-0.008480655492356989f, k1[i], z[i]));
                }
            } else if (s == 2) {
#pragma unroll
                for (int i = 0; i < 16; i++) {
                    k3[i] = kcf[i];
                    zs[i] = fmaf(4.3622954328695815f, kcf[i], fmaf(-6.359448489975075f, k2[i],
                            fmaf(2.8971530571054935f, k1[i], z[i])));
                }
            } else if (s == 3) {
#pragma unroll
                for (int i = 0; i < 16; i++) {
                    k4[i] = kcf[i];
                    zs[i] = fmaf(-0.09249506636175525f, kcf[i], fmaf(7.4955393428898365f, k3[i],
                            fmaf(-11.748883564062828f, k2[i], fmaf(5.325864828439257f, k1[i], z[i]))));
                }
            } else if (s == 4) {
#pragma unroll
                for (int i = 0; i < 16; i++) {
                    k5[i] = kcf[i];
                    zs[i] = fmaf(-0.028269050394068383f, kcf[i], fmaf(-0.071584973281401f, k4[i],
                            fmaf(8.159367898576159f, k3[i], fmaf(-12.92096931784711f, k2[i],
                            fmaf(5.86145544294642f, k1[i], z[i])))));
                }
            } else {
#pragma unroll
                for (int i = 0; i < 16; i++) {
                    z[i] = fmaf(2.324710524099774f, kcf[i], fmaf(-3.290069515436081f, k5[i],
                           fmaf(1.379008574103742f, k4[i], fmaf(0.4798896504144996f, k3[i],
                           fmaf(0.01f, k2[i], fmaf(0.09646076681806523f, k1[i], z[i]))))));
                }
            }
        }
    }

    // ---- Readout: sigmoid(z . w_ro + b_ro); quad reduction over l%4 ----
    {
        float pA = 0.f, pB = 0.f;
#pragma unroll
        for (int t = 0; t < 4; t++) {
            int c = 8 * t + 2 * (lane & 3);
            float w0 = w_ro[c], w1v = w_ro[c + 1];
            pA = fmaf(z[t * 4 + 0], w0, fmaf(z[t * 4 + 1], w1v, pA));
            pB = fmaf(z[t * 4 + 2], w0, fmaf(z[t * 4 + 3], w1v, pB));
        }
        pA += __shfl_xor_sync(0xffffffffu, pA, 1);
        pA += __shfl_xor_sync(0xffffffffu, pA, 2);
        pB += __shfl_xor_sync(0xffffffffu, pB, 1);
        pB += __shfl_xor_sync(0xffffffffu, pB, 2);
        float br0 = b_ro[0];
        if ((lane & 3) == 0) {
            if (vA) out[bA] = __fdividef(1.0f, 1.0f + __expf(-(pA + br0)));
            if (vB) out[bB] = __fdividef(1.0f, 1.0f + __expf(-(pB + br0)));
        }
    }
}

extern "C" void kernel_launch(void* const* d_in, const int* in_sizes, int n_in,
                              void* d_out, int out_size) {
    const float* times = (const float*)d_in[0];
    const float* grads = (const float*)d_in[1];
    const float* w1    = (const float*)d_in[2];
    const float* b1    = (const float*)d_in[3];
    const float* w2    = (const float*)d_in[4];
    const float* b2    = (const float*)d_in[5];
    const float* w3    = (const float*)d_in[6];
    const float* b3    = (const float*)d_in[7];
    const float* w_enc = (const float*)d_in[8];
    const float* b_enc = (const float*)d_in[9];
    const float* w_ro  = (const float*)d_in[10];
    const float* b_ro  = (const float*)d_in[11];
    float* out = (float*)d_out;

    int T = in_sizes[0];
    int B = in_sizes[1] / (T * CINC);

    cudaFuncSetAttribute(cde_hmma_kernel, cudaFuncAttributeMaxDynamicSharedMemorySize, SMEM_BYTES);

    int blocks = (B + CTAB - 1) / CTAB;   // 256
    cde_hmma_kernel<<<blocks, NTH, SMEM_BYTES>>>(times, grads, w1, b1, w2, b2, w3, b3,
                                                 w_enc, b_enc, w_ro, b_ro, out, B, T);
}

// round 8
// speedup vs baseline: 6.2454x; 1.8471x over previous
#include <cuda_runtime.h>
#include <cstdint>
#include <cstddef>

#define CINC  3
#define WARPS 4
#define MB    16               // batches per warp (one m16 tile)
#define CTAB  (WARPS * MB)     // 64
#define NTH   (WARPS * 32)

// ---- smem layout (bytes) ----
// B-fragments: per (plane, ntile, ktile): 32 lanes x uint2 (b0,b1) = 256B ; 2 planes
#define BF1_OFF 0              // 2*8*2*256  = 8192
#define BF2_OFF 8192           // 2*8*4*256  = 16384
#define BF3_OFF 24576          // 2*12*4*256 = 24576
#define B1E_OFF 49152          // 8*32*8 = 2048
#define B2E_OFF 51200          // 2048
#define B3E_OFF 53248          // 12*32*8 = 3072
#define SMEM_BYTES 56320

__device__ __forceinline__ float hi16f(uint32_t u) { return __uint_as_float(u & 0xFFFF0000u); }

// bf16 (top-16-bits) of plane p of the 2-way truncation split of v, as low 16 bits
__device__ __forceinline__ uint32_t bf_plane(float v, int p) {
    uint32_t u = __float_as_uint(v);
    if (p == 0) return u >> 16;
    float r = v - hi16f(u);
    return __float_as_uint(r) >> 16;
}

// split two fp32 into packed bf16x2 words for 2 planes (low half = first value)
__device__ __forceinline__ void split_pair(float va, float vb, uint32_t& p0, uint32_t& p1) {
    uint32_t Aa = __float_as_uint(va), Ab = __float_as_uint(vb);
    float ra = va - hi16f(Aa), rb = vb - hi16f(Ab);
    uint32_t Ra = __float_as_uint(ra), Rb = __float_as_uint(rb);
    p0 = __byte_perm(Aa, Ab, 0x7632);
    p1 = __byte_perm(Ra, Rb, 0x7632);
}

__device__ __forceinline__ float fast_tanh(float x) {
    float e = __expf(2.0f * x);
    return 1.0f - __fdividef(2.0f, e + 1.0f);
}

__device__ __forceinline__ void mma_bf16(float* d, const uint32_t* a, uint32_t b0, uint32_t b1) {
    asm volatile("mma.sync.aligned.m16n8k16.row.col.f32.bf16.bf16.f32 "
                 "{%0,%1,%2,%3}, {%4,%5,%6,%7}, {%8,%9}, {%0,%1,%2,%3};"
                 : "+f"(d[0]), "+f"(d[1]), "+f"(d[2]), "+f"(d[3])
                 : "r"(a[0]), "r"(a[1]), "r"(a[2]), "r"(a[3]), "r"(b0), "r"(b1));
}

// One split-GEMM layer: D[NT][4] = bias + 3 bf16 products (A0B0 + A1B0 + A0B1).
// B loaded once per (pb, kt, nt): pb=0 -> pa 0,1 ; pb=1 -> pa 0.
template<int NT, int KT>
__device__ __forceinline__ void run_gemm(float (*D)[4], const uint2* frags,
                                         const float2* biasE,
                                         const uint32_t A[2][4][4], int lane) {
#pragma unroll
    for (int nt = 0; nt < NT; nt++) {
        float2 bb = biasE[nt * 32 + lane];
        D[nt][0] = bb.x; D[nt][1] = bb.y; D[nt][2] = bb.x; D[nt][3] = bb.y;
    }
#pragma unroll
    for (int pb = 0; pb < 2; pb++) {
#pragma unroll
        for (int kt = 0; kt < KT; kt++) {
#pragma unroll
            for (int nt = 0; nt < NT; nt++) {
                uint2 Bv = frags[((pb * NT + nt) * KT + kt) * 32 + lane];
                mma_bf16(D[nt], A[0][kt], Bv.x, Bv.y);
                if (pb == 0) mma_bf16(D[nt], A[1][kt], Bv.x, Bv.y);
            }
        }
    }
}

// Epilogue for an 8-ntile layer: tanh(D) -> 2-plane A fragments (ktile q from ntiles 2q,2q+1)
__device__ __forceinline__ void epilogue_tanh(const float (*D)[4], uint32_t A[2][4][4]) {
#pragma unroll
    for (int q = 0; q < 4; q++) {
        float t0 = fast_tanh(D[2 * q][0]), t1 = fast_tanh(D[2 * q][1]);
        split_pair(t0, t1, A[0][q][0], A[1][q][0]);
        t0 = fast_tanh(D[2 * q][2]); t1 = fast_tanh(D[2 * q][3]);
        split_pair(t0, t1, A[0][q][1], A[1][q][1]);
        t0 = fast_tanh(D[2 * q + 1][0]); t1 = fast_tanh(D[2 * q + 1][1]);
        split_pair(t0, t1, A[0][q][2], A[1][q][2]);
        t0 = fast_tanh(D[2 * q + 1][2]); t1 = fast_tanh(D[2 * q + 1][3]);
        split_pair(t0, t1, A[0][q][3], A[1][q][3]);
    }
}

__global__ void __launch_bounds__(NTH, 2) cde_hmma_kernel(
    const float* __restrict__ times,
    const float* __restrict__ grads,
    const float* __restrict__ w1, const float* __restrict__ b1,
    const float* __restrict__ w2, const float* __restrict__ b2,
    const float* __restrict__ w3, const float* __restrict__ b3,
    const float* __restrict__ w_enc, const float* __restrict__ b_enc,
    const float* __restrict__ w_ro, const float* __restrict__ b_ro,
    float* __restrict__ out, int B, int T)
{
    extern __shared__ char sm[];
    int tid = threadIdx.x;
    int lane = tid & 31, warp = tid >> 5;

    // ---- Build B-fragment planes + expanded biases in smem ----
    // Layer1: W1 64x32
    for (int idx = tid; idx < 2 * 8 * 2 * 32; idx += NTH) {
        int ln = idx & 31, f = idx >> 5;
        int kt = f % 2, nt = (f / 2) % 8, p = f / 16;
        int n = nt * 8 + ln / 4, k0 = kt * 16 + 2 * (ln & 3);
        const float* wr = w1 + n * 32;
        uint32_t l0 = bf_plane(wr[k0], p),     l1 = bf_plane(wr[k0 + 1], p);
        uint32_t h0 = bf_plane(wr[k0 + 8], p), h1 = bf_plane(wr[k0 + 9], p);
        ((uint2*)(sm + BF1_OFF))[f * 32 + ln] = make_uint2(l0 | (l1 << 16), h0 | (h1 << 16));
    }
    // Layer2: W2 64x64
    for (int idx = tid; idx < 2 * 8 * 4 * 32; idx += NTH) {
        int ln = idx & 31, f = idx >> 5;
        int kt = f % 4, nt = (f / 4) % 8, p = f / 32;
        int n = nt * 8 + ln / 4, k0 = kt * 16 + 2 * (ln & 3);
        const float* wr = w2 + n * 64;
        uint32_t l0 = bf_plane(wr[k0], p),     l1 = bf_plane(wr[k0 + 1], p);
        uint32_t h0 = bf_plane(wr[k0 + 8], p), h1 = bf_plane(wr[k0 + 9], p);
        ((uint2*)(sm + BF2_OFF))[f * 32 + ln] = make_uint2(l0 | (l1 << 16), h0 | (h1 << 16));
    }
    // Layer3: W3 96x64, rows PERMUTED: logical n' = h + 32*ch  <-  original row 3h+ch
    for (int idx = tid; idx < 2 * 12 * 4 * 32; idx += NTH) {
        int ln = idx & 31, f = idx >> 5;
        int kt = f % 4, nt = (f / 4) % 12, p = f / 48;
        int np = nt * 8 + ln / 4;                 // logical col 0..95
        int row = 3 * (np & 31) + (np >> 5);      // original W3 row
        int k0 = kt * 16 + 2 * (ln & 3);
        const float* wr = w3 + row * 64;
        uint32_t l0 = bf_plane(wr[k0], p),     l1 = bf_plane(wr[k0 + 1], p);
        uint32_t h0 = bf_plane(wr[k0 + 8], p), h1 = bf_plane(wr[k0 + 9], p);
        ((uint2*)(sm + BF3_OFF))[f * 32 + ln] = make_uint2(l0 | (l1 << 16), h0 | (h1 << 16));
    }
    // Expanded biases: biasE[nt*32+lane] = {b[8nt+2(l%4)], b[8nt+2(l%4)+1]}
    for (int idx = tid; idx < 8 * 32; idx += NTH) {
        int ln = idx & 31, nt = idx >> 5;
        int c = 8 * nt + 2 * (ln & 3);
        ((float2*)(sm + B1E_OFF))[idx] = make_float2(b1[c], b1[c + 1]);
        ((float2*)(sm + B2E_OFF))[idx] = make_float2(b2[c], b2[c + 1]);
    }
    for (int idx = tid; idx < 12 * 32; idx += NTH) {
        int ln = idx & 31, nt = idx >> 5;
        int c = 8 * nt + 2 * (ln & 3);                 // logical n'
        int i0 = 3 * (c & 31) + (c >> 5);              // original b3 idx
        int c1v = c + 1;
        int i1 = 3 * (c1v & 31) + (c1v >> 5);
        ((float2*)(sm + B3E_OFF))[idx] = make_float2(b3[i0], b3[i1]);
    }
    __syncthreads();

    const uint2* bf1 = (const uint2*)(sm + BF1_OFF);
    const uint2* bf2 = (const uint2*)(sm + BF2_OFF);
    const uint2* bf3 = (const uint2*)(sm + BF3_OFF);
    const float2* be1 = (const float2*)(sm + B1E_OFF);
    const float2* be2 = (const float2*)(sm + B2E_OFF);
    const float2* be3 = (const float2*)(sm + B3E_OFF);

    // ---- per-warp batch rows ----
    int base = blockIdx.x * CTAB + warp * MB;
    int bA = base + (lane >> 2);          // rows l/4      (c0,c1)
    int bB = bA + 8;                      // rows l/4 + 8  (c2,c3)
    bool vA = bA < B, vB = bB < B;
    const float* gA = grads + (size_t)(vA ? bA : 0) * (size_t)T * CINC;
    const float* gB = grads + (size_t)(vB ? bB : 0) * (size_t)T * CINC;

    float dt = times[1] - times[0];

    // ---- state in D-fragment layout: elem (t,c): col = 8t+2(l%4)+(c&1), row per c ----
    float z[16], k1[16], k2[16], k3[16], k4[16], k5[16], zs[16];
#pragma unroll
    for (int t = 0; t < 4; t++) {
        int c = 8 * t + 2 * (lane & 3);
        float v0 = w_enc[c] + b_enc[c];
        float v1 = w_enc[c + 1] + b_enc[c + 1];
        z[t * 4 + 0] = v0; z[t * 4 + 1] = v1; z[t * 4 + 2] = v0; z[t * 4 + 3] = v1;
    }

    uint32_t As[2][4][4], An[2][4][4];   // ping-pong A fragments (2 planes)

#pragma unroll 1
    for (int n = 0; n < T - 1; n++) {
        float dqA[3], dqB[3];
#pragma unroll
        for (int c = 0; c < 3; c++) {
            dqA[c] = gA[n * 3 + c] * dt;
            dqB[c] = gB[n * 3 + c] * dt;
        }

#pragma unroll
        for (int i = 0; i < 16; i++) zs[i] = z[i];

#pragma unroll 1
        for (int s = 0; s < 6; s++) {
            // build A1 (K=32 -> ktiles 0,1) from zs; D-frag -> A-frag is lane-local
#pragma unroll
            for (int j = 0; j < 2; j++) {
                split_pair(zs[(2 * j) * 4 + 0], zs[(2 * j) * 4 + 1], As[0][j][0], As[1][j][0]);
                split_pair(zs[(2 * j) * 4 + 2], zs[(2 * j) * 4 + 3], As[0][j][1], As[1][j][1]);
                split_pair(zs[(2 * j + 1) * 4 + 0], zs[(2 * j + 1) * 4 + 1], As[0][j][2], As[1][j][2]);
                split_pair(zs[(2 * j + 1) * 4 + 2], zs[(2 * j + 1) * 4 + 3], As[0][j][3], As[1][j][3]);
            }

            // ---- GEMM1: (16x32)@W1^T -> 16x64 ----
            {
                float D[8][4];
                run_gemm<8, 2>(D, bf1, be1, As, lane);
                epilogue_tanh(D, An);
            }
            // ---- GEMM2: (16x64)@W2^T -> 16x64 ----
            {
                float D[8][4];
                run_gemm<8, 4>(D, bf2, be2, An, lane);
                epilogue_tanh(D, As);
            }
            // ---- GEMM3: (16x64)@W3p^T -> 16x96 (grouped; contract with dq per channel) ----
            float kc[4][4];
#pragma unroll
            for (int g = 0; g < 3; g++) {
                float D[4][4];
#pragma unroll
                for (int i = 0; i < 4; i++) {
                    float2 bb = be3[(g * 4 + i) * 32 + lane];
                    D[i][0] = bb.x; D[i][1] = bb.y; D[i][2] = bb.x; D[i][3] = bb.y;
                }
#pragma unroll
                for (int pb = 0; pb < 2; pb++) {
#pragma unroll
                    for (int kt = 0; kt < 4; kt++) {
#pragma unroll
                        for (int i = 0; i < 4; i++) {
                            uint2 Bv = bf3[((pb * 12 + g * 4 + i) * 4 + kt) * 32 + lane];
                            mma_bf16(D[i], As[0][kt], Bv.x, Bv.y);
                            if (pb == 0) mma_bf16(D[i], As[1][kt], Bv.x, Bv.y);
                        }
                    }
                }
                float dA = dqA[g], dB = dqB[g];
                if (g == 0) {
#pragma unroll
                    for (int i = 0; i < 4; i++) {
                        kc[i][0] = D[i][0] * dA; kc[i][1] = D[i][1] * dA;
                        kc[i][2] = D[i][2] * dB; kc[i][3] = D[i][3] * dB;
                    }
                } else {
#pragma unroll
                    for (int i = 0; i < 4; i++) {
                        kc[i][0] = fmaf(D[i][0], dA, kc[i][0]); kc[i][1] = fmaf(D[i][1], dA, kc[i][1]);
                        kc[i][2] = fmaf(D[i][2], dB, kc[i][2]); kc[i][3] = fmaf(D[i][3], dB, kc[i][3]);
                    }
                }
            }
            float* kcf = &kc[0][0];

            // ---- Tsit5 stage combine ----
            if (s == 0) {
#pragma unroll
                for (int i = 0; i < 16; i++) { k1[i] = kcf[i]; zs[i] = fmaf(0.161f, kcf[i], z[i]); }
            } else if (s == 1) {
#pragma unroll
                for (int i = 0; i < 16; i++) {
                    k2[i] = kcf[i];
                    zs[i] = fmaf(0.335480655492357f, kcf[i], fmaf(-0.008480655492356989f, k1[i], z[i]));
                }
            } else if (s == 2) {
#pragma unroll
                for (int i = 0; i < 16; i++) {
                    k3[i] = kcf[i];
                    zs[i] = fmaf(4.3622954328695815f, kcf[i], fmaf(-6.359448489975075f, k2[i],
                            fmaf(2.8971530571054935f, k1[i], z[i])));
                }
            } else if (s == 3) {
#pragma unroll
                for (int i = 0; i < 16; i++) {
                    k4[i] = kcf[i];
                    zs[i] = fmaf(-0.09249506636175525f, kcf[i], fmaf(7.4955393428898365f, k3[i],
                            fmaf(-11.748883564062828f, k2[i], fmaf(5.325864828439257f, k1[i], z[i]))));
                }
            } else if (s == 4) {
#pragma unroll
                for (int i = 0; i < 16; i++) {
                    k5[i] = kcf[i];
                    zs[i] = fmaf(-0.028269050394068383f, kcf[i], fmaf(-0.071584973281401f, k4[i],
                            fmaf(8.159367898576159f, k3[i], fmaf(-12.92096931784711f, k2[i],
                            fmaf(5.86145544294642f, k1[i], z[i])))));
                }
            } else {
#pragma unroll
                for (int i = 0; i < 16; i++) {
                    z[i] = fmaf(2.324710524099774f, kcf[i], fmaf(-3.290069515436081f, k5[i],
                           fmaf(1.379008574103742f, k4[i], fmaf(0.4798896504144996f, k3[i],
                           fmaf(0.01f, k2[i], fmaf(0.09646076681806523f, k1[i], z[i]))))));
                }
            }
        }
    }

    // ---- Readout: sigmoid(z . w_ro + b_ro); quad reduction over l%4 ----
    {
        float pA = 0.f, pB = 0.f;
#pragma unroll
        for (int t = 0; t < 4; t++) {
            int c = 8 * t + 2 * (lane & 3);
            float w0 = w_ro[c], w1v = w_ro[c + 1];
            pA = fmaf(z[t * 4 + 0], w0, fmaf(z[t * 4 + 1], w1v, pA));
            pB = fmaf(z[t * 4 + 2], w0, fmaf(z[t * 4 + 3], w1v, pB));
        }
        pA += __shfl_xor_sync(0xffffffffu, pA, 1);
        pA += __shfl_xor_sync(0xffffffffu, pA, 2);
        pB += __shfl_xor_sync(0xffffffffu, pB, 1);
        pB += __shfl_xor_sync(0xffffffffu, pB, 2);
        float br0 = b_ro[0];
        if ((lane & 3) == 0) {
            if (vA) out[bA] = __fdividef(1.0f, 1.0f + __expf(-(pA + br0)));
            if (vB) out[bB] = __fdividef(1.0f, 1.0f + __expf(-(pB + br0)));
        }
    }
}

extern "C" void kernel_launch(void* const* d_in, const int* in_sizes, int n_in,
                              void* d_out, int out_size) {
    const float* times = (const float*)d_in[0];
    const float* grads = (const float*)d_in[1];
    const float* w1    = (const float*)d_in[2];
    const float* b1    = (const float*)d_in[3];
    const float* w2    = (const float*)d_in[4];
    const float* b2    = (const float*)d_in[5];
    const float* w3    = (const float*)d_in[6];
    const float* b3    = (const float*)d_in[7];
    const float* w_enc = (const float*)d_in[8];
    const float* b_enc = (const float*)d_in[9];
    const float* w_ro  = (const float*)d_in[10];
    const float* b_ro  = (const float*)d_in[11];
    float* out = (float*)d_out;

    int T = in_sizes[0];
    int B = in_sizes[1] / (T * CINC);

    cudaFuncSetAttribute(cde_hmma_kernel, cudaFuncAttributeMaxDynamicSharedMemorySize, SMEM_BYTES);

    int blocks = (B + CTAB - 1) / CTAB;   // 256
    cde_hmma_kernel<<<blocks, NTH, SMEM_BYTES>>>(times, grads, w1, b1, w2, b2, w3, b3,
                                                 w_enc, b_enc, w_ro, b_ro, out, B, T);
}

// round 11
// speedup vs baseline: 6.2653x; 1.0032x over previous
#include <cuda_runtime.h>
#include <cstdint>
#include <cstddef>

#define CINC  3
#define WARPS 4
#define MB    16               // batches per warp (one m16 tile)
#define CTAB  (WARPS * MB)     // 64
#define NTH   (WARPS * 32)

// ---- smem layout (bytes) ----
#define BF1_OFF 0              // 2*8*2*256  = 8192
#define BF2_OFF 8192           // 2*8*4*256  = 16384
#define BF3_OFF 24576          // 2*12*4*256 = 24576
#define B1E_OFF 49152          // 2048
#define B2E_OFF 51200          // 2048
#define B3E_OFF 53248          // 3072
#define SMEM_BYTES 56320

__device__ __forceinline__ float hi16f(uint32_t u) { return __uint_as_float(u & 0xFFFF0000u); }

__device__ __forceinline__ uint32_t bf_plane(float v, int p) {
    uint32_t u = __float_as_uint(v);
    if (p == 0) return u >> 16;
    float r = v - hi16f(u);
    return __float_as_uint(r) >> 16;
}

__device__ __forceinline__ void split_pair(float va, float vb, uint32_t& p0, uint32_t& p1) {
    uint32_t Aa = __float_as_uint(va), Ab = __float_as_uint(vb);
    float ra = va - hi16f(Aa), rb = vb - hi16f(Ab);
    uint32_t Ra = __float_as_uint(ra), Rb = __float_as_uint(rb);
    p0 = __byte_perm(Aa, Ab, 0x7632);
    p1 = __byte_perm(Ra, Rb, 0x7632);
}

__device__ __forceinline__ float fast_tanh(float x) {
    float e = __expf(2.0f * x);
    return 1.0f - __fdividef(2.0f, e + 1.0f);
}

__device__ __forceinline__ void mma_bf16(float* d, const uint32_t* a, uint32_t b0, uint32_t b1) {
    asm volatile("mma.sync.aligned.m16n8k16.row.col.f32.bf16.bf16.f32 "
                 "{%0,%1,%2,%3}, {%4,%5,%6,%7}, {%8,%9}, {%0,%1,%2,%3};"
                 : "+f"(d[0]), "+f"(d[1]), "+f"(d[2]), "+f"(d[3])
                 : "r"(a[0]), "r"(a[1]), "r"(a[2]), "r"(a[3]), "r"(b0), "r"(b1));
}

// GEMM1 MMAs for nt in [LO,HI): all pb,kt -> D[nt] COMPLETE after call (early epilogue)
template<int LO, int HI>
__device__ __forceinline__ void g1_mma(float (*D)[4], const uint2* frags,
                                       const uint32_t A[2][4][4], int lane) {
#pragma unroll
    for (int pb = 0; pb < 2; pb++)
#pragma unroll
        for (int kt = 0; kt < 2; kt++)
#pragma unroll
            for (int nt = LO; nt < HI; nt++) {
                uint2 Bv = frags[((pb * 8 + nt) * 2 + kt) * 32 + lane];
                mma_bf16(D[nt], A[0][kt], Bv.x, Bv.y);
                if (pb == 0) mma_bf16(D[nt], A[1][kt], Bv.x, Bv.y);
            }
}

// GEMM2 MMAs for kt in [KLO,KHI): consumes only A ktiles [KLO,KHI) (early start)
template<int KLO, int KHI>
__device__ __forceinline__ void g2_mma(float (*D)[4], const uint2* frags,
                                       const uint32_t A[2][4][4], int lane) {
#pragma unroll
    for (int pb = 0; pb < 2; pb++)
#pragma unroll
        for (int kt = KLO; kt < KHI; kt++)
#pragma unroll
            for (int nt = 0; nt < 8; nt++) {
                uint2 Bv = frags[((pb * 8 + nt) * 4 + kt) * 32 + lane];
                mma_bf16(D[nt], A[0][kt], Bv.x, Bv.y);
                if (pb == 0) mma_bf16(D[nt], A[1][kt], Bv.x, Bv.y);
            }
}

// Epilogue half: ktiles Q0, Q0+1 (from ntiles 2q, 2q+1)
template<int Q0>
__device__ __forceinline__ void epi_half(const float (*D)[4], uint32_t A[2][4][4]) {
#pragma unroll
    for (int q = Q0; q < Q0 + 2; q++) {
        float t0 = fast_tanh(D[2 * q][0]), t1 = fast_tanh(D[2 * q][1]);
        split_pair(t0, t1, A[0][q][0], A[1][q][0]);
        t0 = fast_tanh(D[2 * q][2]); t1 = fast_tanh(D[2 * q][3]);
        split_pair(t0, t1, A[0][q][1], A[1][q][1]);
        t0 = fast_tanh(D[2 * q + 1][0]); t1 = fast_tanh(D[2 * q + 1][1]);
        split_pair(t0, t1, A[0][q][2], A[1][q][2]);
        t0 = fast_tanh(D[2 * q + 1][2]); t1 = fast_tanh(D[2 * q + 1][3]);
        split_pair(t0, t1, A[0][q][3], A[1][q][3]);
    }
}

__global__ void __launch_bounds__(NTH, 2) cde_hmma_kernel(
    const float* __restrict__ times,
    const float* __restrict__ grads,
    const float* __restrict__ w1, const float* __restrict__ b1,
    const float* __restrict__ w2, const float* __restrict__ b2,
    const float* __restrict__ w3, const float* __restrict__ b3,
    const float* __restrict__ w_enc, const float* __restrict__ b_enc,
    const float* __restrict__ w_ro, const float* __restrict__ b_ro,
    float* __restrict__ out, int B, int T)
{
    extern __shared__ char sm[];
    int tid = threadIdx.x;
    int lane = tid & 31, warp = tid >> 5;

    // ---- Build B-fragment planes + expanded biases in smem ----
    for (int idx = tid; idx < 2 * 8 * 2 * 32; idx += NTH) {
        int ln = idx & 31, f = idx >> 5;
        int kt = f % 2, nt = (f / 2) % 8, p = f / 16;
        int n = nt * 8 + ln / 4, k0 = kt * 16 + 2 * (ln & 3);
        const float* wr = w1 + n * 32;
        uint32_t l0 = bf_plane(wr[k0], p),     l1 = bf_plane(wr[k0 + 1], p);
        uint32_t h0 = bf_plane(wr[k0 + 8], p), h1 = bf_plane(wr[k0 + 9], p);
        ((uint2*)(sm + BF1_OFF))[f * 32 + ln] = make_uint2(l0 | (l1 << 16), h0 | (h1 << 16));
    }
    for (int idx = tid; idx < 2 * 8 * 4 * 32; idx += NTH) {
        int ln = idx & 31, f = idx >> 5;
        int kt = f % 4, nt = (f / 4) % 8, p = f / 32;
        int n = nt * 8 + ln / 4, k0 = kt * 16 + 2 * (ln & 3);
        const float* wr = w2 + n * 64;
        uint32_t l0 = bf_plane(wr[k0], p),     l1 = bf_plane(wr[k0 + 1], p);
        uint32_t h0 = bf_plane(wr[k0 + 8], p), h1 = bf_plane(wr[k0 + 9], p);
        ((uint2*)(sm + BF2_OFF))[f * 32 + ln] = make_uint2(l0 | (l1 << 16), h0 | (h1 << 16));
    }
    for (int idx = tid; idx < 2 * 12 * 4 * 32; idx += NTH) {
        int ln = idx & 31, f = idx >> 5;
        int kt = f % 4, nt = (f / 4) % 12, p = f / 48;
        int np = nt * 8 + ln / 4;
        int row = 3 * (np & 31) + (np >> 5);      // permuted: logical n' = h + 32*ch
        int k0 = kt * 16 + 2 * (ln & 3);
        const float* wr = w3 + row * 64;
        uint32_t l0 = bf_plane(wr[k0], p),     l1 = bf_plane(wr[k0 + 1], p);
        uint32_t h0 = bf_plane(wr[k0 + 8], p), h1 = bf_plane(wr[k0 + 9], p);
        ((uint2*)(sm + BF3_OFF))[f * 32 + ln] = make_uint2(l0 | (l1 << 16), h0 | (h1 << 16));
    }
    for (int idx = tid; idx < 8 * 32; idx += NTH) {
        int ln = idx & 31, nt = idx >> 5;
        int c = 8 * nt + 2 * (ln & 3);
        ((float2*)(sm + B1E_OFF))[idx] = make_float2(b1[c], b1[c + 1]);
        ((float2*)(sm + B2E_OFF))[idx] = make_float2(b2[c], b2[c + 1]);
    }
    for (int idx = tid; idx < 12 * 32; idx += NTH) {
        int ln = idx & 31, nt = idx >> 5;
        int c = 8 * nt + 2 * (ln & 3);
        int i0 = 3 * (c & 31) + (c >> 5);
        int c1v = c + 1;
        int i1 = 3 * (c1v & 31) + (c1v >> 5);
        ((float2*)(sm + B3E_OFF))[idx] = make_float2(b3[i0], b3[i1]);
    }
    __syncthreads();

    const uint2* bf1 = (const uint2*)(sm + BF1_OFF);
    const uint2* bf2 = (const uint2*)(sm + BF2_OFF);
    const uint2* bf3 = (const uint2*)(sm + BF3_OFF);
    const float2* be1 = (const float2*)(sm + B1E_OFF);
    const float2* be2 = (const float2*)(sm + B2E_OFF);
    const float2* be3 = (const float2*)(sm + B3E_OFF);

    int base = blockIdx.x * CTAB + warp * MB;
    int bA = base + (lane >> 2);
    int bB = bA + 8;
    bool vA = bA < B, vB = bB < B;
    const float* gA = grads + (size_t)(vA ? bA : 0) * (size_t)T * CINC;
    const float* gB = grads + (size_t)(vB ? bB : 0) * (size_t)T * CINC;

    float dt = times[1] - times[0];

    float z[16], k1[16], k2[16], k3[16], k4[16], k5[16], zs[16];
#pragma unroll
    for (int t = 0; t < 4; t++) {
        int c = 8 * t + 2 * (lane & 3);
        float v0 = w_enc[c] + b_enc[c];
        float v1 = w_enc[c + 1] + b_enc[c + 1];
        z[t * 4 + 0] = v0; z[t * 4 + 1] = v1; z[t * 4 + 2] = v0; z[t * 4 + 3] = v1;
    }

    uint32_t As[2][4][4], An[2][4][4];

    // gradient software prefetch (hide 577-cyc DRAM latency behind a full step)
    float pgA[3], pgB[3];
#pragma unroll
    for (int c = 0; c < 3; c++) { pgA[c] = gA[c]; pgB[c] = gB[c]; }

#pragma unroll 1
    for (int n = 0; n < T - 1; n++) {
        float dqA[3], dqB[3];
#pragma unroll
        for (int c = 0; c < 3; c++) {
            dqA[c] = pgA[c] * dt;
            dqB[c] = pgB[c] * dt;
        }
        int np = (n + 1 < T - 1) ? (n + 1) : n;
#pragma unroll
        for (int c = 0; c < 3; c++) {
            pgA[c] = gA[np * 3 + c];
            pgB[c] = gB[np * 3 + c];
        }

#pragma unroll
        for (int i = 0; i < 16; i++) zs[i] = z[i];

#pragma unroll 1
        for (int s = 0; s < 6; s++) {
            // build A1 fragments (K=32 -> ktiles 0,1) from zs; lane-local
#pragma unroll
            for (int j = 0; j < 2; j++) {
                split_pair(zs[(2 * j) * 4 + 0], zs[(2 * j) * 4 + 1], As[0][j][0], As[1][j][0]);
                split_pair(zs[(2 * j) * 4 + 2], zs[(2 * j) * 4 + 3], As[0][j][1], As[1][j][1]);
                split_pair(zs[(2 * j + 1) * 4 + 0], zs[(2 * j + 1) * 4 + 1], As[0][j][2], As[1][j][2]);
                split_pair(zs[(2 * j + 1) * 4 + 2], zs[(2 * j + 1) * 4 + 3], As[0][j][3], As[1][j][3]);
            }

            // ---- GEMM1 (16x32 @ W1^T -> 16x64), nt-grouped for early epilogue ----
            float D[8][4];
#pragma unroll
            for (int nt = 0; nt < 8; nt++) {
                float2 bb = be1[nt * 32 + lane];
                D[nt][0] = bb.x; D[nt][1] = bb.y; D[nt][2] = bb.x; D[nt][3] = bb.y;
            }
            g1_mma<0, 4>(D, bf1, As, lane);
            g1_mma<4, 8>(D, bf1, As, lane);     // overlaps with epi of D[0..3] below
            epi_half<0>(D, An);                 // An ktiles 0,1 ready early
            epi_half<2>(D, An);

            // ---- GEMM2 (16x64 @ W2^T -> 16x64), kt-split: kt{0,1} needs only An kt0,1 ----
            float E[8][4];
#pragma unroll
            for (int nt = 0; nt < 8; nt++) {
                float2 bb = be2[nt * 32 + lane];
                E[nt][0] = bb.x; E[nt][1] = bb.y; E[nt][2] = bb.x; E[nt][3] = bb.y;
            }
            g2_mma<0, 2>(E, bf2, An, lane);
            g2_mma<2, 4>(E, bf2, An, lane);
            epi_half<0>(E, As);                 // As ktiles 0,1 ready early
            epi_half<2>(E, As);

            // ---- GEMM3 (16x64 @ W3p^T -> 16x96), per channel group, kt-split ----
            float kc[4][4];
#pragma unroll
            for (int g = 0; g < 3; g++) {
                float F[4][4];
#pragma unroll
                for (int i = 0; i < 4; i++) {
                    float2 bb = be3[(g * 4 + i) * 32 + lane];
                    F[i][0] = bb.x; F[i][1] = bb.y; F[i][2] = bb.x; F[i][3] = bb.y;
                }
#pragma unroll
                for (int kh = 0; kh < 2; kh++) {        // kt halves {0,1}, {2,3}
#pragma unroll
                    for (int pb = 0; pb < 2; pb++) {
#pragma unroll
                        for (int kt = 2 * kh; kt < 2 * kh + 2; kt++) {
#pragma unroll
                            for (int i = 0; i < 4; i++) {
                                uint2 Bv = bf3[((pb * 12 + g * 4 + i) * 4 + kt) * 32 + lane];
                                mma_bf16(F[i], As[0][kt], Bv.x, Bv.y);
                                if (pb == 0) mma_bf16(F[i], As[1][kt], Bv.x, Bv.y);
                            }
                        }
                    }
                }
                float dA = dqA[g], dB = dqB[g];
                if (g == 0) {
#pragma unroll
                    for (int i = 0; i < 4; i++) {
                        kc[i][0] = F[i][0] * dA; kc[i][1] = F[i][1] * dA;
                        kc[i][2] = F[i][2] * dB; kc[i][3] = F[i][3] * dB;
                    }
                } else {
#pragma unroll
                    for (int i = 0; i < 4; i++) {
                        kc[i][0] = fmaf(F[i][0], dA, kc[i][0]); kc[i][1] = fmaf(F[i][1], dA, kc[i][1]);
                        kc[i][2] = fmaf(F[i][2], dB, kc[i][2]); kc[i][3] = fmaf(F[i][3], dB, kc[i][3]);
                    }
                }
            }
            float* kcf = &kc[0][0];

            // ---- Tsit5 stage combine ----
            if (s == 0) {
#pragma unroll
                for (int i = 0; i < 16; i++) { k1[i] = kcf[i]; zs[i] = fmaf(0.161f, kcf[i], z[i]); }
            } else if (s == 1) {
#pragma unroll
                for (int i = 0; i < 16; i++) {
                    k2[i] = kcf[i];
                    zs[i] = fmaf(0.335480655492357f, kcf[i], fmaf(-0.008480655492356989f, k1[i], z[i]));
                }
            } else if (s == 2) {
#pragma unroll
                for (int i = 0; i < 16; i++) {
                    k3[i] = kcf[i];
                    zs[i] = fmaf(4.3622954328695815f, kcf[i], fmaf(-6.359448489975075f, k2[i],
                            fmaf(2.8971530571054935f, k1[i], z[i])));
                }
            } else if (s == 3) {
#pragma unroll
                for (int i = 0; i < 16; i++) {
                    k4[i] = kcf[i];
                    zs[i] = fmaf(-0.09249506636175525f, kcf[i], fmaf(7.4955393428898365f, k3[i],
                            fmaf(-11.748883564062828f, k2[i], fmaf(5.325864828439257f, k1[i], z[i]))));
                }
            } else if (s == 4) {
#pragma unroll
                for (int i = 0; i < 16; i++) {
                    k5[i] = kcf[i];
                    zs[i] = fmaf(-0.028269050394068383f, kcf[i], fmaf(-0.071584973281401f, k4[i],
                            fmaf(8.159367898576159f, k3[i], fmaf(-12.92096931784711f, k2[i],
                            fmaf(5.86145544294642f, k1[i], z[i])))));
                }
            } else {
#pragma unroll
                for (int i = 0; i < 16; i++) {
                    z[i] = fmaf(2.324710524099774f, kcf[i], fmaf(-3.290069515436081f, k5[i],
                           fmaf(1.379008574103742f, k4[i], fmaf(0.4798896504144996f, k3[i],
                           fmaf(0.01f, k2[i], fmaf(0.09646076681806523f, k1[i], z[i]))))));
                }
            }
        }
    }

    // ---- Readout: sigmoid(z . w_ro + b_ro); quad reduction over l%4 ----
    {
        float pA = 0.f, pB = 0.f;
#pragma unroll
        for (int t = 0; t < 4; t++) {
            int c = 8 * t + 2 * (lane & 3);
            float w0 = w_ro[c], w1v = w_ro[c + 1];
            pA = fmaf(z[t * 4 + 0], w0, fmaf(z[t * 4 + 1], w1v, pA));
            pB = fmaf(z[t * 4 + 2], w0, fmaf(z[t * 4 + 3], w1v, pB));
        }
        pA += __shfl_xor_sync(0xffffffffu, pA, 1);
        pA += __shfl_xor_sync(0xffffffffu, pA, 2);
        pB += __shfl_xor_sync(0xffffffffu, pB, 1);
        pB += __shfl_xor_sync(0xffffffffu, pB, 2);
        float br0 = b_ro[0];
        if ((lane & 3) == 0) {
            if (vA) out[bA] = __fdividef(1.0f, 1.0f + __expf(-(pA + br0)));
            if (vB) out[bB] = __fdividef(1.0f, 1.0f + __expf(-(pB + br0)));
        }
    }
}

extern "C" void kernel_launch(void* const* d_in, const int* in_sizes, int n_in,
                              void* d_out, int out_size) {
    const float* times = (const float*)d_in[0];
    const float* grads = (const float*)d_in[1];
    const float* w1    = (const float*)d_in[2];
    const float* b1    = (const float*)d_in[3];
    const float* w2    = (const float*)d_in[4];
    const float* b2    = (const float*)d_in[5];
    const float* w3    = (const float*)d_in[6];
    const float* b3    = (const float*)d_in[7];
    const float* w_enc = (const float*)d_in[8];
    const float* b_enc = (const float*)d_in[9];
    const float* w_ro  = (const float*)d_in[10];
    const float* b_ro  = (const float*)d_in[11];
    float* out = (float*)d_out;

    int T = in_sizes[0];
    int B = in_sizes[1] / (T * CINC);

    cudaFuncSetAttribute(cde_hmma_kernel, cudaFuncAttributeMaxDynamicSharedMemorySize, SMEM_BYTES);

    int blocks = (B + CTAB - 1) / CTAB;   // 256
    cde_hmma_kernel<<<blocks, NTH, SMEM_BYTES>>>(times, grads, w1, b1, w2, b2, w3, b3,
                                                 w_enc, b_enc, w_ro, b_ro, out, B, T);
}